// round 16
// baseline (speedup 1.0000x reference)
#include <cuda_runtime.h>
#include <cuda_fp16.h>
#include <cstdint>
#include <cstddef>

// ---------------- problem constants ----------------
#define BB     32
#define CIN    192
#define HH     56
#define WWD    56
#define HP     58
#define WP     58
#define COUTN  192
#define KDIM   1728          // CIN * 9
#define HWN    3136          // 56*56
#define NPIX   100352        // BB*HWN

// ---------------- tiling ----------------
#define MTILE   128                // pixels per CTA
#define NBLK    (NPIX / MTILE)     // 784 exactly
#define KC      64                 // K halves per sub-chunk (128 B rows)
#define NCHUNK  27                 // 1728 / 64
#define NFULLP  13                 // full pairs (chunks 0..25); chunk 26 is the tail

// smem stage layout (stage = 2 sub-chunks)
#define A_OFF(s)  ((uint32_t)(s) * 16384)            // 128 x 128B each
#define B_OFF(s)  (32768u + (uint32_t)(s) * 24576)   // 192 x 128B each
#define STAGE_BYTES 81920          // 80 KB
#define SMEM_HDR    1024           // bias at [0..768)
#define SMEM_TOTAL  (SMEM_HDR + 2 * STAGE_BYTES)   // 164864

// ---------------- device scratch (zero-initialized at module load; ----------------
// padded borders of x are never written -> stay zero, deterministic)
__device__ __align__(16) __half g_xhi[(size_t)BB * HP * WP * CIN];
__device__ __align__(16) __half g_whi[(size_t)COUTN * KDIM];

// ---------------- helpers ----------------
__device__ __forceinline__ uint32_t smem_u32(const void* p) {
    uint32_t a;
    asm("{ .reg .u64 t; cvta.to.shared.u64 t, %1; cvt.u32.u64 %0, t; }" : "=r"(a) : "l"(p));
    return a;
}

__device__ __forceinline__ uint32_t sw128(uint32_t off) {
    return off ^ ((off >> 3) & 0x70);
}

__device__ __forceinline__ void cpa16(uint32_t dst, const void* src) {
    asm volatile("cp.async.cg.shared.global [%0], [%1], 16;" :: "r"(dst), "l"(src) : "memory");
}

#define CP_COMMIT()  asm volatile("cp.async.commit_group;" ::: "memory")
#define CP_WAIT(N)   asm volatile("cp.async.wait_group %0;" :: "n"(N) : "memory")

__device__ __forceinline__ void ldsm4(uint32_t* r, uint32_t addr) {
    asm volatile("ldmatrix.sync.aligned.m8n8.x4.shared.b16 {%0,%1,%2,%3}, [%4];"
                 : "=r"(r[0]), "=r"(r[1]), "=r"(r[2]), "=r"(r[3]) : "r"(addr));
}

__device__ __forceinline__ void mma_f16(float* c, const uint32_t* a, const uint32_t* b) {
    asm volatile(
        "mma.sync.aligned.m16n8k16.row.col.f32.f16.f16.f32 "
        "{%0,%1,%2,%3}, {%4,%5,%6,%7}, {%8,%9}, {%0,%1,%2,%3};"
        : "+f"(c[0]), "+f"(c[1]), "+f"(c[2]), "+f"(c[3])
        : "r"(a[0]), "r"(a[1]), "r"(a[2]), "r"(a[3]), "r"(b[0]), "r"(b[1]));
}

// ---------------- merged prep kernel (vectorized 8B stores) ----------------
// blockIdx.y < 6 : x NCHW fp32 -> NHWC padded fp16, 32c x 64hw transpose tile,
//                  each thread packs 4 consecutive channels -> one 8B store
// blockIdx.y == 6: weights -> fp16, K reordered (kn = (i*3+j)*192 + c)
__global__ void prep_kernel(const float* __restrict__ x, const float* __restrict__ w) {
    if (blockIdx.y == 6) {
        int idx = (blockIdx.z * 49 + blockIdx.x) * 256 + threadIdx.x;
        if (idx < COUTN * KDIM) {
            int o  = idx / KDIM;
            int kn = idx - o * KDIM;
            int r  = kn / CIN;
            int c  = kn - r * CIN;
            g_whi[idx] = __float2half_rn(w[o * KDIM + c * 9 + r]);
        }
        return;
    }

    __shared__ float tile[32][65];
    int b   = blockIdx.z;
    int hw0 = blockIdx.x * 64;
    int c0  = blockIdx.y * 32;
    int tid = threadIdx.x;

    // load: 32 channels x 64 hw, coalesced along hw (4B per thread x 8)
    const float* src = x + ((size_t)b * CIN + c0) * HWN + hw0;
#pragma unroll
    for (int it = 0; it < 8; it++) {
        int idx = tid + it * 256;
        int r   = idx >> 6;          // channel 0..31
        int col = idx & 63;          // hw 0..63
        tile[r][col] = src[(size_t)r * HWN + col];
    }
    __syncthreads();

    // store: each thread converts 4 consecutive channels of one pixel and
    // writes them as a single 8B (half4) store. 512 items = 2 iters x 256.
    // Banks: word addr = (4*c4+k)*65 + hwl -> bank (4*c4 + k + hwl) mod 32,
    // unique across lanes for fixed k => conflict-free.
#pragma unroll
    for (int it = 0; it < 2; it++) {
        int idx = tid + it * 256;
        int hwl = idx >> 3;          // hw 0..63
        int c4  = idx & 7;           // channel group 0..7 (4 channels each)
        int hw  = hw0 + hwl;
        int h   = hw / WWD;
        int w2  = hw - h * WWD;
        __half2 lo = __floats2half2_rn(tile[c4 * 4 + 0][hwl], tile[c4 * 4 + 1][hwl]);
        __half2 hi = __floats2half2_rn(tile[c4 * 4 + 2][hwl], tile[c4 * 4 + 3][hwl]);
        size_t dst = (((size_t)b * HP + (h + 1)) * WP + (w2 + 1)) * CIN + c0 + c4 * 4;
        __half2 pack[2] = { lo, hi };
        *(uint2*)(g_xhi + dst) = *(const uint2*)pack;
    }
}

// ---------------- main kernel: im2col GEMM via mma.sync (HMMA fp32 acc) ----------------
// CTA: 128 pixels x 192 couts, 8 warps = 2(M) x 4(N), warp tile 64x48.
// Fragments double-buffered with COMPILE-TIME buffer indices (full unroll) so
// they live in registers; ldsm of step q+1 hides under the mma burst of q.
// (Byte-identical math/schedule to the R12 champion.)
__global__ void __launch_bounds__(256, 1)
conv_main_kernel(const float* __restrict__ bias, float* __restrict__ out) {
    extern __shared__ __align__(1024) char smem[];
    uint32_t su = smem_u32(smem);
    int tid  = threadIdx.x;
    int lane = tid & 31;
    int wid  = tid >> 5;
    int blk  = blockIdx.x;

    float* s_bias = (float*)smem;
    if (tid < COUTN) s_bias[tid] = bias[tid];

    // ---- per-thread cp.async geometry (256 threads) ----
    int vr = tid & 7;     // 16B chunk within a 128B row
    int r0 = tid >> 3;    // 0..31 row slot
    int rbase[4];
#pragma unroll
    for (int it = 0; it < 4; it++) {
        int p   = blk * MTILE + r0 + it * 32;
        int b   = p / HWN;
        int rem = p - b * HWN;
        int h   = rem / WWD;
        int w   = rem - h * WWD;
        rbase[it] = ((b * HP + h) * WP + w) * CIN;
    }

    auto issue_chunk = [&](int u, uint32_t sb, int s) {
        int ij = u / 3;
        int c0 = (u - ij * 3) * KC;
        int i  = ij / 3;
        int j  = ij - i * 3;
        int coff = (i * WP + j) * CIN + c0;
        // A: 128 rows x 128B
#pragma unroll
        for (int it = 0; it < 4; it++) {
            int m = r0 + it * 32;
            uint32_t sw = sw128((uint32_t)m * 128 + vr * 16);
            int go = rbase[it] + coff + vr * 8;
            cpa16(sb + A_OFF(s) + sw, g_xhi + go);
        }
        // B: 192 rows x 128B
#pragma unroll
        for (int it = 0; it < 6; it++) {
            int o = r0 + it * 32;
            uint32_t sw = sw128((uint32_t)o * 128 + vr * 16);
            size_t go = (size_t)o * KDIM + (size_t)u * KC + vr * 8;
            cpa16(sb + B_OFF(s) + sw, g_whi + go);
        }
    };

    // ---- per-thread mma geometry ----
    int wm = (wid >> 2) * 64;      // warp M offset (0 or 64)
    int wn = (wid & 3) * 48;       // warp N offset (0..144)
    int a_r = lane & 15;
    int a_k = (lane >> 4) * 16;    // bytes
    int b_r = (lane & 7) + ((lane >> 4) << 3);
    int b_k = ((lane >> 3) & 1) * 16;

    float acc[4][6][4];
#pragma unroll
    for (int mt = 0; mt < 4; mt++)
#pragma unroll
        for (int nt = 0; nt < 6; nt++)
#pragma unroll
            for (int q = 0; q < 4; q++) acc[mt][nt][q] = 0.0f;

    // fragment double buffers (indices always compile-time constants)
    uint32_t ahi[2][4][4], bhi[2][3][4];

#define LDFR(sbase, Q, BUF)                                                     \
    do {                                                                        \
        const int _s  = (Q) >> 2;                                               \
        const uint32_t _kb = (uint32_t)((Q) & 3) * 32;                          \
        _Pragma("unroll")                                                       \
        for (int mt = 0; mt < 4; mt++) {                                        \
            uint32_t off = (uint32_t)(wm + mt * 16 + a_r) * 128 + _kb + a_k;    \
            ldsm4(ahi[BUF][mt], (sbase) + A_OFF(_s) + sw128(off));              \
        }                                                                       \
        _Pragma("unroll")                                                       \
        for (int nb = 0; nb < 3; nb++) {                                        \
            uint32_t off = (uint32_t)(wn + nb * 16 + b_r) * 128 + _kb + b_k;    \
            ldsm4(bhi[BUF][nb], (sbase) + B_OFF(_s) + sw128(off));              \
        }                                                                       \
    } while (0)

#define BURST(BUF)                                                              \
    do {                                                                        \
        _Pragma("unroll")                                                       \
        for (int mt = 0; mt < 4; mt++)                                          \
            _Pragma("unroll")                                                   \
            for (int nt = 0; nt < 6; nt++)                                      \
                mma_f16(acc[mt][nt], ahi[BUF][mt], &bhi[BUF][nt >> 1][(nt & 1) * 2]); \
    } while (0)

    auto issue_pair = [&](int p, int stage) {
        uint32_t sb = su + SMEM_HDR + (uint32_t)stage * STAGE_BYTES;
        issue_chunk(2 * p, sb, 0);
        if (2 * p + 1 < NCHUNK) issue_chunk(2 * p + 1, sb, 1);
        CP_COMMIT();
    };

    // ---- mainloop: 13 full pairs (chunks 0..25), then tail chunk 26 ----
    issue_pair(0, 0);

    for (int p = 0; p < NFULLP; p++) {
        CP_WAIT(0);                 // pair p's group is the only one outstanding
        __syncthreads();            // pair p resident; other stage free

        issue_pair(p + 1, (p + 1) & 1);   // p+1 <= 13 == tail pair (chunk 26)

        uint32_t sb = su + SMEM_HDR + (uint32_t)(p & 1) * STAGE_BYTES;
        LDFR(sb, 0, 0);
        LDFR(sb, 1, 1); BURST(0);
        LDFR(sb, 2, 0); BURST(1);
        LDFR(sb, 3, 1); BURST(0);
        LDFR(sb, 4, 0); BURST(1);
        LDFR(sb, 5, 1); BURST(0);
        LDFR(sb, 6, 0); BURST(1);
        LDFR(sb, 7, 1); BURST(0);
        BURST(1);
    }

    // tail: chunk 26 in stage NFULLP&1 = 1, slot 0 (4 q-steps)
    {
        CP_WAIT(0);
        __syncthreads();
        uint32_t sb = su + SMEM_HDR + (uint32_t)(NFULLP & 1) * STAGE_BYTES;
        LDFR(sb, 0, 0);
        LDFR(sb, 1, 1); BURST(0);
        LDFR(sb, 2, 0); BURST(1);
        LDFR(sb, 3, 1); BURST(0);
        BURST(1);
    }

    // ---- epilogue: out[b][cout][hw] = acc + bias ----
    int pix0 = blk * MTILE + wm;
#pragma unroll
    for (int mt = 0; mt < 4; mt++) {
#pragma unroll
        for (int half = 0; half < 2; half++) {
            int p   = pix0 + mt * 16 + half * 8 + (lane >> 2);
            int b   = p / HWN;
            int hw  = p - b * HWN;
            float* ob = out + (size_t)b * COUTN * HWN + hw;
#pragma unroll
            for (int nt = 0; nt < 6; nt++) {
                int n = wn + nt * 8 + (lane & 3) * 2;
                ob[(size_t)n * HWN]       = acc[mt][nt][half * 2 + 0] + s_bias[n];
                ob[(size_t)(n + 1) * HWN] = acc[mt][nt][half * 2 + 1] + s_bias[n + 1];
            }
        }
    }
}

// ---------------- launch ----------------
extern "C" void kernel_launch(void* const* d_in, const int* in_sizes, int n_in,
                              void* d_out, int out_size) {
    const float* x    = (const float*)d_in[0];
    const float* w    = (const float*)d_in[1];
    const float* bias = (const float*)d_in[2];
    float* out        = (float*)d_out;
    (void)in_sizes; (void)n_in; (void)out_size;

    cudaFuncSetAttribute(conv_main_kernel,
                         cudaFuncAttributeMaxDynamicSharedMemorySize, SMEM_TOTAL);

    prep_kernel<<<dim3(HWN / 64, 7, BB), 256>>>(x, w);
    conv_main_kernel<<<NBLK, 256, SMEM_TOTAL>>>(bias, out);
}

// round 17
// speedup vs baseline: 1.4890x; 1.4890x over previous
#include <cuda_runtime.h>
#include <cuda_fp16.h>
#include <cstdint>
#include <cstddef>

// ---------------- problem constants ----------------
#define BB     32
#define CIN    192
#define HH     56
#define WWD    56
#define HP     58
#define WP     58
#define COUTN  192
#define KDIM   1728          // CIN * 9
#define HWN    3136          // 56*56
#define NPIX   100352        // BB*HWN

// ---------------- tiling ----------------
#define MTILE   128                // pixels per CTA
#define NBLK    (NPIX / MTILE)     // 784 exactly
#define KC      64                 // K halves per sub-chunk (128 B rows)
#define NCHUNK  27                 // 1728 / 64
#define NFULLP  13                 // full pairs (chunks 0..25); chunk 26 is the tail

// smem stage layout (stage = 2 sub-chunks)
#define A_OFF(s)  ((uint32_t)(s) * 16384)            // 128 x 128B each
#define B_OFF(s)  (32768u + (uint32_t)(s) * 24576)   // 192 x 128B each
#define STAGE_BYTES 81920          // 80 KB
#define SMEM_HDR    1024           // bias at [0..768)
#define SMEM_TOTAL  (SMEM_HDR + 2 * STAGE_BYTES)   // 164864

// ---------------- device scratch (zero-initialized at module load; ----------------
// padded borders of x are never written -> stay zero, deterministic)
__device__ __align__(16) __half g_xhi[(size_t)BB * HP * WP * CIN];
__device__ __align__(16) __half g_whi[(size_t)COUTN * KDIM];

// ---------------- helpers ----------------
__device__ __forceinline__ uint32_t smem_u32(const void* p) {
    uint32_t a;
    asm("{ .reg .u64 t; cvta.to.shared.u64 t, %1; cvt.u32.u64 %0, t; }" : "=r"(a) : "l"(p));
    return a;
}

__device__ __forceinline__ uint32_t sw128(uint32_t off) {
    return off ^ ((off >> 3) & 0x70);
}

__device__ __forceinline__ void cpa16(uint32_t dst, const void* src) {
    asm volatile("cp.async.cg.shared.global [%0], [%1], 16;" :: "r"(dst), "l"(src) : "memory");
}

#define CP_COMMIT()  asm volatile("cp.async.commit_group;" ::: "memory")
#define CP_WAIT(N)   asm volatile("cp.async.wait_group %0;" :: "n"(N) : "memory")

__device__ __forceinline__ void ldsm4(uint32_t* r, uint32_t addr) {
    asm volatile("ldmatrix.sync.aligned.m8n8.x4.shared.b16 {%0,%1,%2,%3}, [%4];"
                 : "=r"(r[0]), "=r"(r[1]), "=r"(r[2]), "=r"(r[3]) : "r"(addr));
}

__device__ __forceinline__ void mma_f16(float* c, const uint32_t* a, const uint32_t* b) {
    asm volatile(
        "mma.sync.aligned.m16n8k16.row.col.f32.f16.f16.f32 "
        "{%0,%1,%2,%3}, {%4,%5,%6,%7}, {%8,%9}, {%0,%1,%2,%3};"
        : "+f"(c[0]), "+f"(c[1]), "+f"(c[2]), "+f"(c[3])
        : "r"(a[0]), "r"(a[1]), "r"(a[2]), "r"(a[3]), "r"(b[0]), "r"(b[1]));
}

// ---------------- merged prep kernel (vectorized 8B stores) ----------------
// blockIdx.y < 6 : x NCHW fp32 -> NHWC padded fp16, 32c x 64hw transpose tile,
//                  each thread packs 4 consecutive channels -> one 8B store
// blockIdx.y == 6: weights -> fp16, K reordered (kn = (i*3+j)*192 + c)
__global__ void prep_kernel(const float* __restrict__ x, const float* __restrict__ w) {
    if (blockIdx.y == 6) {
        int idx = (blockIdx.z * 49 + blockIdx.x) * 256 + threadIdx.x;
        if (idx < COUTN * KDIM) {
            int o  = idx / KDIM;
            int kn = idx - o * KDIM;
            int r  = kn / CIN;
            int c  = kn - r * CIN;
            g_whi[idx] = __float2half_rn(w[o * KDIM + c * 9 + r]);
        }
        return;
    }

    __shared__ float tile[32][65];
    int b   = blockIdx.z;
    int hw0 = blockIdx.x * 64;
    int c0  = blockIdx.y * 32;
    int tid = threadIdx.x;

    // load: 32 channels x 64 hw, coalesced along hw (4B per thread x 8)
    const float* src = x + ((size_t)b * CIN + c0) * HWN + hw0;
#pragma unroll
    for (int it = 0; it < 8; it++) {
        int idx = tid + it * 256;
        int r   = idx >> 6;          // channel 0..31
        int col = idx & 63;          // hw 0..63
        tile[r][col] = src[(size_t)r * HWN + col];
    }
    __syncthreads();

    // store: each thread converts 4 consecutive channels of one pixel and
    // writes them as a single 8B (half4) store. 512 items = 2 iters x 256.
#pragma unroll
    for (int it = 0; it < 2; it++) {
        int idx = tid + it * 256;
        int hwl = idx >> 3;          // hw 0..63
        int c4  = idx & 7;           // channel group 0..7 (4 channels each)
        int hw  = hw0 + hwl;
        int h   = hw / WWD;
        int w2  = hw - h * WWD;
        __half2 lo = __floats2half2_rn(tile[c4 * 4 + 0][hwl], tile[c4 * 4 + 1][hwl]);
        __half2 hi = __floats2half2_rn(tile[c4 * 4 + 2][hwl], tile[c4 * 4 + 3][hwl]);
        size_t dst = (((size_t)b * HP + (h + 1)) * WP + (w2 + 1)) * CIN + c0 + c4 * 4;
        __half2 pack[2] = { lo, hi };
        *(uint2*)(g_xhi + dst) = *(const uint2*)pack;
    }
}

// ---------------- main kernel: im2col GEMM via mma.sync (HMMA fp32 acc) ----------------
// CTA: 128 pixels x 192 couts, 8 warps = 2(M) x 4(N), warp tile 64x48.
// Fragments double-buffered with COMPILE-TIME buffer indices (full unroll) so
// they live in registers; ldsm of step q+1 hides under the mma burst of q.
// (Byte-identical math/schedule to the R12 champion.)
__global__ void __launch_bounds__(256, 1)
conv_main_kernel(const float* __restrict__ bias, float* __restrict__ out) {
    extern __shared__ __align__(1024) char smem[];
    uint32_t su = smem_u32(smem);
    int tid  = threadIdx.x;
    int lane = tid & 31;
    int wid  = tid >> 5;
    int blk  = blockIdx.x;

    float* s_bias = (float*)smem;
    if (tid < COUTN) s_bias[tid] = bias[tid];

    // ---- per-thread cp.async geometry (256 threads) ----
    int vr = tid & 7;     // 16B chunk within a 128B row
    int r0 = tid >> 3;    // 0..31 row slot
    int rbase[4];
#pragma unroll
    for (int it = 0; it < 4; it++) {
        int p   = blk * MTILE + r0 + it * 32;
        int b   = p / HWN;
        int rem = p - b * HWN;
        int h   = rem / WWD;
        int w   = rem - h * WWD;
        rbase[it] = ((b * HP + h) * WP + w) * CIN;
    }

    auto issue_chunk = [&](int u, uint32_t sb, int s) {
        int ij = u / 3;
        int c0 = (u - ij * 3) * KC;
        int i  = ij / 3;
        int j  = ij - i * 3;
        int coff = (i * WP + j) * CIN + c0;
        // A: 128 rows x 128B
#pragma unroll
        for (int it = 0; it < 4; it++) {
            int m = r0 + it * 32;
            uint32_t sw = sw128((uint32_t)m * 128 + vr * 16);
            int go = rbase[it] + coff + vr * 8;
            cpa16(sb + A_OFF(s) + sw, g_xhi + go);
        }
        // B: 192 rows x 128B
#pragma unroll
        for (int it = 0; it < 6; it++) {
            int o = r0 + it * 32;
            uint32_t sw = sw128((uint32_t)o * 128 + vr * 16);
            size_t go = (size_t)o * KDIM + (size_t)u * KC + vr * 8;
            cpa16(sb + B_OFF(s) + sw, g_whi + go);
        }
    };

    // ---- per-thread mma geometry ----
    int wm = (wid >> 2) * 64;      // warp M offset (0 or 64)
    int wn = (wid & 3) * 48;       // warp N offset (0..144)
    int a_r = lane & 15;
    int a_k = (lane >> 4) * 16;    // bytes
    int b_r = (lane & 7) + ((lane >> 4) << 3);
    int b_k = ((lane >> 3) & 1) * 16;

    float acc[4][6][4];
#pragma unroll
    for (int mt = 0; mt < 4; mt++)
#pragma unroll
        for (int nt = 0; nt < 6; nt++)
#pragma unroll
            for (int q = 0; q < 4; q++) acc[mt][nt][q] = 0.0f;

    // fragment double buffers (indices always compile-time constants)
    uint32_t ahi[2][4][4], bhi[2][3][4];

#define LDFR(sbase, Q, BUF)                                                     \
    do {                                                                        \
        const int _s  = (Q) >> 2;                                               \
        const uint32_t _kb = (uint32_t)((Q) & 3) * 32;                          \
        _Pragma("unroll")                                                       \
        for (int mt = 0; mt < 4; mt++) {                                        \
            uint32_t off = (uint32_t)(wm + mt * 16 + a_r) * 128 + _kb + a_k;    \
            ldsm4(ahi[BUF][mt], (sbase) + A_OFF(_s) + sw128(off));              \
        }                                                                       \
        _Pragma("unroll")                                                       \
        for (int nb = 0; nb < 3; nb++) {                                        \
            uint32_t off = (uint32_t)(wn + nb * 16 + b_r) * 128 + _kb + b_k;    \
            ldsm4(bhi[BUF][nb], (sbase) + B_OFF(_s) + sw128(off));              \
        }                                                                       \
    } while (0)

#define BURST(BUF)                                                              \
    do {                                                                        \
        _Pragma("unroll")                                                       \
        for (int mt = 0; mt < 4; mt++)                                          \
            _Pragma("unroll")                                                   \
            for (int nt = 0; nt < 6; nt++)                                      \
                mma_f16(acc[mt][nt], ahi[BUF][mt], &bhi[BUF][nt >> 1][(nt & 1) * 2]); \
    } while (0)

    auto issue_pair = [&](int p, int stage) {
        uint32_t sb = su + SMEM_HDR + (uint32_t)stage * STAGE_BYTES;
        issue_chunk(2 * p, sb, 0);
        if (2 * p + 1 < NCHUNK) issue_chunk(2 * p + 1, sb, 1);
        CP_COMMIT();
    };

    // ---- mainloop: 13 full pairs (chunks 0..25), then tail chunk 26 ----
    issue_pair(0, 0);

    for (int p = 0; p < NFULLP; p++) {
        CP_WAIT(0);                 // pair p's group is the only one outstanding
        __syncthreads();            // pair p resident; other stage free

        issue_pair(p + 1, (p + 1) & 1);   // p+1 <= 13 == tail pair (chunk 26)

        uint32_t sb = su + SMEM_HDR + (uint32_t)(p & 1) * STAGE_BYTES;
        LDFR(sb, 0, 0);
        LDFR(sb, 1, 1); BURST(0);
        LDFR(sb, 2, 0); BURST(1);
        LDFR(sb, 3, 1); BURST(0);
        LDFR(sb, 4, 0); BURST(1);
        LDFR(sb, 5, 1); BURST(0);
        LDFR(sb, 6, 0); BURST(1);
        LDFR(sb, 7, 1); BURST(0);
        BURST(1);
    }

    // tail: chunk 26 in stage NFULLP&1 = 1, slot 0 (4 q-steps)
    {
        CP_WAIT(0);
        __syncthreads();
        uint32_t sb = su + SMEM_HDR + (uint32_t)(NFULLP & 1) * STAGE_BYTES;
        LDFR(sb, 0, 0);
        LDFR(sb, 1, 1); BURST(0);
        LDFR(sb, 2, 0); BURST(1);
        LDFR(sb, 3, 1); BURST(0);
        BURST(1);
    }

    // ---- epilogue: out[b][cout][hw] = acc + bias ----
    int pix0 = blk * MTILE + wm;
#pragma unroll
    for (int mt = 0; mt < 4; mt++) {
#pragma unroll
        for (int half = 0; half < 2; half++) {
            int p   = pix0 + mt * 16 + half * 8 + (lane >> 2);
            int b   = p / HWN;
            int hw  = p - b * HWN;
            float* ob = out + (size_t)b * COUTN * HWN + hw;
#pragma unroll
            for (int nt = 0; nt < 6; nt++) {
                int n = wn + nt * 8 + (lane & 3) * 2;
                ob[(size_t)n * HWN]       = acc[mt][nt][half * 2 + 0] + s_bias[n];
                ob[(size_t)(n + 1) * HWN] = acc[mt][nt][half * 2 + 1] + s_bias[n + 1];
            }
        }
    }
}

// ---------------- launch ----------------
extern "C" void kernel_launch(void* const* d_in, const int* in_sizes, int n_in,
                              void* d_out, int out_size) {
    const float* x    = (const float*)d_in[0];
    const float* w    = (const float*)d_in[1];
    const float* bias = (const float*)d_in[2];
    float* out        = (float*)d_out;
    (void)in_sizes; (void)n_in; (void)out_size;

    cudaFuncSetAttribute(conv_main_kernel,
                         cudaFuncAttributeMaxDynamicSharedMemorySize, SMEM_TOTAL);

    prep_kernel<<<dim3(HWN / 64, 7, BB), 256>>>(x, w);
    conv_main_kernel<<<NBLK, 256, SMEM_TOTAL>>>(bias, out);
}